// round 6
// baseline (speedup 1.0000x reference)
#include <cuda_runtime.h>
#include <cuda_bf16.h>
#include <cstdint>

// ---------------- problem constants ----------------
#define Bsz 4
#define Nq  100
#define Mt  50
#define HWP 65536
#define KS  64                  // k per stage
#define NKT (HWP / KS)          // 1024 k-tiles per batch
#define CTAS_PER_B 37           // 148 CTAs = one full wave
#define NCTA (CTAS_PER_B * Bsz)
#define THREADS 512             // 16 warps: 9 producers + 7 consumers
#define NPROD 288               // producer threads
#define NCONS 224               // consumer threads
#define DEPTH 3                 // smem ring depth

// per-slot smem: A_x[112x64]bf16-ish padded to 128 rows (16K) | A_s (16K) | B[64x64] (8K)
#define SLOT_SZ 40960
#define SMEM_BYTES (1024 + DEPTH * SLOT_SZ + 1024)

// ---------------- fused scratch (one memset) ----------------
#define OFF_G1   0
#define OFF_G2   (Bsz * Nq * Mt)
#define OFF_SNPM (2 * Bsz * Nq * Mt)
#define OFF_SNSP (2 * Bsz * Nq * Mt + Bsz * Nq)
#define OFF_SMT  (2 * Bsz * Nq * Mt + 2 * Bsz * Nq)
#define OFF_CTR  (2 * Bsz * Nq * Mt + 2 * Bsz * Nq + Bsz * Mt)
#define SCRATCH_N (OFF_CTR + 1)
__device__ float g_s[SCRATCH_N];

__device__ __forceinline__ uint32_t smem_u32(const void* p) {
    uint32_t a;
    asm("{ .reg .u64 t; cvta.to.shared.u64 t, %1; cvt.u32.u64 %0, t; }" : "=r"(a) : "l"(p));
    return a;
}
__device__ __forceinline__ uint32_t SW(uint32_t o) { return o ^ ((o >> 3) & 0x70); }

#define MBAR_INIT(a, c) asm volatile("mbarrier.init.shared.b64 [%0], %1;" :: "r"(a), "r"(c) : "memory")
#define MBAR_ARRIVE(a)  asm volatile("mbarrier.arrive.shared.b64 _, [%0];" :: "r"(a) : "memory")
#define MBAR_WAIT(a, ph) do {                                                         \
    asm volatile("{ .reg .pred P;  WL_%=:                                             \
        mbarrier.try_wait.parity.acquire.cta.shared::cta.b64 P, [%0], %1, 0x989680;   \
        @P bra.uni WD_%=;  bra.uni WL_%=;  WD_%=: }"                                  \
        :: "r"(a), "r"(ph) : "memory"); } while (0)

#define LDSM4(r0, r1, r2, r3, addr) \
    asm volatile("ldmatrix.sync.aligned.m8n8.x4.shared.b16 {%0,%1,%2,%3}, [%4];" \
                 : "=r"(r0), "=r"(r1), "=r"(r2), "=r"(r3) : "r"(addr))

#define MMA16816(c, a, b0, b1) \
    asm volatile("mma.sync.aligned.m16n8k16.row.col.f32.bf16.bf16.f32 " \
                 "{%0,%1,%2,%3},{%4,%5,%6,%7},{%8,%9},{%0,%1,%2,%3};" \
                 : "+f"((c)[0]), "+f"((c)[1]), "+f"((c)[2]), "+f"((c)[3]) \
                 : "r"((a)[0]), "r"((a)[1]), "r"((a)[2]), "r"((a)[3]), "r"(b0), "r"(b1))

__global__ void __launch_bounds__(THREADS, 1)
cost_main(const float* __restrict__ X, const float* __restrict__ T,
          const float* __restrict__ logits, const float* __restrict__ style,
          const int* __restrict__ sids, float* __restrict__ out)
{
    extern __shared__ char dsm[];
    const uint32_t sb = (smem_u32(dsm) + 1023u) & ~1023u;
    __shared__ int slast;

    const int tid = threadIdx.x;
    const int b   = blockIdx.y;
    const int r   = blockIdx.x;
    const int t0  = (r * NKT) / CTAS_PER_B;
    const int nst = ((r + 1) * NKT) / CTAS_PER_B - t0;

    // mbarriers: FULL(i)=sb+16i, EMPTY(i)=sb+16i+8
    if (tid == 0) {
        #pragma unroll
        for (int i = 0; i < DEPTH; i++) {
            MBAR_INIT(sb + 16 * i,     NPROD);   // full
            MBAR_INIT(sb + 16 * i + 8, NCONS);   // empty
        }
    }
    // zero all slots (rows 100..111 of A, 51..63 of B stay zero forever)
    for (int i = tid; i < (DEPTH * SLOT_SZ) / 8; i += THREADS)
        asm volatile("st.shared.b64 [%0], %1;" :: "r"(sb + 1024 + i * 8), "l"(0ull) : "memory");
    __syncthreads();
    // ones rows in every slot: A row 100 (-> sum_k t), B row 50 (-> sum_k sigma)
    const uint64_t ones8 = 0x3F803F803F803F80ull;
    if (tid < 16 * DEPTH) {
        int sl = tid >> 4, q = tid & 15;
        uint32_t base = sb + 1024 + sl * SLOT_SZ;
        asm volatile("st.shared.b64 [%0], %1;"
                     :: "r"(base + SW(100u * 128u + (uint32_t)q * 8u)), "l"(ones8) : "memory");
        asm volatile("st.shared.b64 [%0], %1;"
                     :: "r"(base + 32768u + SW(50u * 128u + (uint32_t)q * 8u)), "l"(ones8) : "memory");
    }
    __syncthreads();

    const float* Xb = X + (size_t)b * Nq * HWP;
    const float* Tb = T + (size_t)b * Mt * HWP;
    const int w = tid >> 5, l = tid & 31;

    if (w < 9) {
        // ================= PRODUCER =================
        float4 a0[6], a1[6], tv[3];
        float spm[6] = {0,0,0,0,0,0}, spl[6] = {0,0,0,0,0,0};

        auto LOADX = [&](int s, float4 (&la)[6]) {
            if (s >= nst) return;
            const int kb = (t0 + s) * KS;
            #pragma unroll
            for (int j = 0; j < 6; j++) {
                int idx = tid + NPROD * j;
                if (idx < 1600) {
                    int row = idx >> 4, c4 = idx & 15;
                    la[j] = *(const float4*)(Xb + (size_t)row * HWP + kb + c4 * 4);
                }
            }
        };
        auto LOADT = [&](int s) {
            if (s >= nst) return;
            const int kb = (t0 + s) * KS;
            #pragma unroll
            for (int j = 0; j < 3; j++) {
                int idx = tid + NPROD * j;
                if (idx < 800) {
                    int row = idx >> 4, c4 = idx & 15;
                    tv[j] = *(const float4*)(Tb + (size_t)row * HWP + kb + c4 * 4);
                }
            }
        };
        auto CONV = [&](float4 (&la)[6], uint32_t BUF) {
            #pragma unroll
            for (int j = 0; j < 6; j++) {
                int idx = tid + NPROD * j;
                if (idx < 1600) {
                    int row = idx >> 4, c4 = idx & 15;
                    float v[4] = {la[j].x, la[j].y, la[j].z, la[j].w};
                    float sg[4];
                    #pragma unroll
                    for (int e = 0; e < 4; e++) {
                        float x = v[e], ea, lg;
                        asm("ex2.approx.f32 %0, %1;" : "=f"(ea) : "f"(-1.4426950408889634f * fabsf(x)));
                        float d = 1.f + ea;
                        asm("lg2.approx.f32 %0, %1;" : "=f"(lg) : "f"(d));
                        spm[j] += fmaxf(x, 0.f);
                        spl[j] += lg;
                        float y = fmaf(-0.4566f, ea, 0.9566f);
                        y = fmaf(y, fmaf(-d, y, 1.f), y);
                        sg[e] = (x >= 0.f) ? y : (1.f - y);
                    }
                    uint32_t xw0, xw1, sw0, sw1;
                    asm("cvt.rn.bf16x2.f32 %0, %1, %2;" : "=r"(xw0) : "f"(v[1]),  "f"(v[0]));
                    asm("cvt.rn.bf16x2.f32 %0, %1, %2;" : "=r"(xw1) : "f"(v[3]),  "f"(v[2]));
                    asm("cvt.rn.bf16x2.f32 %0, %1, %2;" : "=r"(sw0) : "f"(sg[1]), "f"(sg[0]));
                    asm("cvt.rn.bf16x2.f32 %0, %1, %2;" : "=r"(sw1) : "f"(sg[3]), "f"(sg[2]));
                    uint32_t a = BUF + SW((uint32_t)row * 128u + (uint32_t)c4 * 8u);
                    asm volatile("st.shared.v2.b32 [%0], {%1, %2};" :: "r"(a), "r"(xw0), "r"(xw1) : "memory");
                    asm volatile("st.shared.v2.b32 [%0], {%1, %2};" :: "r"(a + 16384u), "r"(sw0), "r"(sw1) : "memory");
                }
            }
            #pragma unroll
            for (int j = 0; j < 3; j++) {
                int idx = tid + NPROD * j;
                if (idx < 800) {
                    int row = idx >> 4, c4 = idx & 15;
                    uint32_t w0, w1;
                    asm("cvt.rn.bf16x2.f32 %0, %1, %2;" : "=r"(w0) : "f"(tv[j].y), "f"(tv[j].x));
                    asm("cvt.rn.bf16x2.f32 %0, %1, %2;" : "=r"(w1) : "f"(tv[j].w), "f"(tv[j].z));
                    uint32_t a = BUF + 32768u + SW((uint32_t)row * 128u + (uint32_t)c4 * 8u);
                    asm volatile("st.shared.v2.b32 [%0], {%1, %2};" :: "r"(a), "r"(w0), "r"(w1) : "memory");
                }
            }
        };

        int stg = 0, ph = 1;   // producer starts phase 1: first DEPTH empty-waits pass
        LOADX(0, a0);
        LOADT(0);
        for (int s = 0; s < nst; s += 2) {
            {   // even stage: conv a0, prefetch x into a1
                MBAR_WAIT(sb + 16 * stg + 8, ph);
                LOADX(s + 1, a1);
                CONV(a0, sb + 1024u + (uint32_t)stg * SLOT_SZ);
                LOADT(s + 1);
                MBAR_ARRIVE(sb + 16 * stg);
                if (++stg == DEPTH) { stg = 0; ph ^= 1; }
            }
            if (s + 1 < nst) {  // odd stage: conv a1, prefetch into a0
                MBAR_WAIT(sb + 16 * stg + 8, ph);
                LOADX(s + 2, a0);
                CONV(a1, sb + 1024u + (uint32_t)stg * SLOT_SZ);
                LOADT(s + 2);
                MBAR_ARRIVE(sb + 16 * stg);
                if (++stg == DEPTH) { stg = 0; ph ^= 1; }
            }
        }
        // softplus row sums
        #pragma unroll
        for (int j = 0; j < 6; j++) {
            int idx = tid + NPROD * j;
            if (idx < 1600)
                atomicAdd(&g_s[OFF_SNSP + b * Nq + (idx >> 4)],
                          spm[j] + 0.6931471805599453f * spl[j]);
        }
    } else {
        // ================= CONSUMER =================
        const int cw = w - 9;                        // 0..6, rows 16cw..16cw+15
        const uint32_t rowA = (uint32_t)(16 * cw + (l & 15)) * 128u + (uint32_t)(l >> 4) * 16u;
        const uint32_t rB   = (uint32_t)(l & 15) * 128u + (uint32_t)(l >> 4) * 16u;

        float cx[7][4], cs[7][4];
        #pragma unroll
        for (int nb = 0; nb < 7; nb++)
            #pragma unroll
            for (int e = 0; e < 4; e++) { cx[nb][e] = 0.f; cs[nb][e] = 0.f; }

        int stg = 0, ph = 0;
        for (int s = 0; s < nst; s++) {
            MBAR_WAIT(sb + 16 * stg, ph);
            const uint32_t BUF = sb + 1024u + (uint32_t)stg * SLOT_SZ;
            const uint32_t BT  = BUF + 32768u;
            #pragma unroll
            for (int i = 0; i < 4; i++) {
                uint32_t ko = 32u * i;
                uint32_t ax[4], as[4], q0[4], q1[4], q2[4], q3[4];
                LDSM4(ax[0], ax[1], ax[2], ax[3], BUF + SW(rowA + ko));
                LDSM4(as[0], as[1], as[2], as[3], BUF + 16384u + SW(rowA + ko));
                LDSM4(q0[0], q0[1], q0[2], q0[3], BT + SW(rB + ko));
                LDSM4(q1[0], q1[1], q1[2], q1[3], BT + SW(rB + 16u * 128u + ko));
                LDSM4(q2[0], q2[1], q2[2], q2[3], BT + SW(rB + 32u * 128u + ko));
                LDSM4(q3[0], q3[1], q3[2], q3[3], BT + SW(rB + 48u * 128u + ko));
                MMA16816(cx[0], ax, q0[0], q0[2]);
                MMA16816(cs[0], as, q0[0], q0[2]);
                MMA16816(cx[1], ax, q0[1], q0[3]);
                MMA16816(cs[1], as, q0[1], q0[3]);
                MMA16816(cx[2], ax, q1[0], q1[2]);
                MMA16816(cs[2], as, q1[0], q1[2]);
                MMA16816(cx[3], ax, q1[1], q1[3]);
                MMA16816(cs[3], as, q1[1], q1[3]);
                MMA16816(cx[4], ax, q2[0], q2[2]);
                MMA16816(cs[4], as, q2[0], q2[2]);
                MMA16816(cx[5], ax, q2[1], q2[3]);
                MMA16816(cs[5], as, q2[1], q2[3]);
                MMA16816(cx[6], ax, q3[0], q3[2]);
                MMA16816(cs[6], as, q3[0], q3[2]);
            }
            MBAR_ARRIVE(sb + 16 * stg + 8);
            if (++stg == DEPTH) { stg = 0; ph ^= 1; }
        }

        // emission
        auto emit = [&](int rr, int m, float vx, float vs) {
            if (rr < Nq) {
                if (m < Mt) {
                    atomicAdd(&g_s[OFF_G1 + (b * Nq + rr) * Mt + m], vx);
                    atomicAdd(&g_s[OFF_G2 + (b * Nq + rr) * Mt + m], vs);
                } else if (m == Mt) {
                    atomicAdd(&g_s[OFF_SNPM + b * Nq + rr], vs);
                }
            } else if (rr == Nq && m < Mt) {
                atomicAdd(&g_s[OFF_SMT + b * Mt + m], vx);
            }
        };
        #pragma unroll
        for (int nb = 0; nb < 7; nb++) {
            const int m0 = nb * 8 + (l & 3) * 2;
            const int r0 = 16 * cw + (l >> 2);
            emit(r0,     m0,     cx[nb][0], cs[nb][0]);
            emit(r0,     m0 + 1, cx[nb][1], cs[nb][1]);
            emit(r0 + 8, m0,     cx[nb][2], cs[nb][2]);
            emit(r0 + 8, m0 + 1, cx[nb][3], cs[nb][3]);
        }
    }

    // ---- grid-wide completion: last CTA runs the epilogue ----
    __threadfence();
    __syncthreads();
    if (tid == 0) {
        int v = atomicAdd((int*)(g_s + OFF_CTR), 1);
        slast = (v == NCTA - 1);
    }
    __syncthreads();
    if (slast) {
        __threadfence();
        for (int i = tid; i < Bsz * Nq * Mt; i += THREADS) {
            const int m  = i % Mt;
            const int n  = (i / Mt) % Nq;
            const int bb = i / (Nq * Mt);

            const float l0 = logits[(bb * Nq + n) * 2 + 0];
            const float l1 = logits[(bb * Nq + n) * 2 + 1];
            const float p1 = __fdividef(1.f, 1.f + __expf(l0 - l1));

            const float* st = style + (bb * Nq + n) * 4;
            const float s0 = st[0], s1 = st[1], s2 = st[2], s3 = st[3];
            const float mx = fmaxf(fmaxf(s0, s1), fmaxf(s2, s3));
            const float e0 = __expf(s0 - mx), e1 = __expf(s1 - mx);
            const float e2 = __expf(s2 - mx), e3 = __expf(s3 - mx);
            const float inv = __fdividef(1.f, e0 + e1 + e2 + e3);

            const float snsp = g_s[OFF_SNSP + bb * Nq + n];
            const float snpm = g_s[OFF_SNPM + bb * Nq + n];
            const float G1v  = g_s[OFF_G1 + (bb * Nq + n) * Mt + m];
            const float G2v  = g_s[OFF_G2 + (bb * Nq + n) * Mt + m];
            const float smt  = g_s[OFF_SMT + bb * Mt + m];

            const float cmask = (snsp - G1v) * (1.0f / (float)HWP);
            const float cdice = 1.f - __fdividef(2.f * G2v + 1.f, snpm + smt + 1.f);

            int sid = sids[bb * Mt + m];
            sid = sid < 0 ? 0 : (sid > 3 ? 3 : sid);
            float pr = (sid == 0) ? e0 : (sid == 1) ? e1 : (sid == 2) ? e2 : e3;
            pr *= inv;

            float c = -2.f * p1 + 5.f * cmask + 5.f * cdice - pr;
            if (!isfinite(c)) c = isnan(c) ? 10000.f : (c > 0.f ? 10000.f : -10000.f);
            out[(bb * Nq + n) * Mt + m] = c;
        }
    }
}

extern "C" void kernel_launch(void* const* d_in, const int* in_sizes, int n_in,
                              void* d_out, int out_size)
{
    const float* pred_logits = (const float*)d_in[0];  // [4,100,2]
    const float* pred_masks  = (const float*)d_in[1];  // [4,100,256,256]
    const float* pred_style  = (const float*)d_in[2];  // [4,100,4]
    const float* tgt_masks   = (const float*)d_in[3];  // [4,50,256,256]
    const int*   styles      = (const int*)d_in[4];    // [4,50]
    float* out = (float*)d_out;                        // [4,100,50]

    cudaFuncSetAttribute(cost_main, cudaFuncAttributeMaxDynamicSharedMemorySize, SMEM_BYTES);

    void* scratch = nullptr;
    cudaGetSymbolAddress(&scratch, g_s);
    cudaMemsetAsync(scratch, 0, SCRATCH_N * sizeof(float), 0);

    dim3 gmain(CTAS_PER_B, Bsz);
    cost_main<<<gmain, THREADS, SMEM_BYTES>>>(pred_masks, tgt_masks,
                                              pred_logits, pred_style, styles, out);
}